// round 12
// baseline (speedup 1.0000x reference)
#include <cuda_runtime.h>
#include <cstdint>

#define NROWS 16384
#define DDIM  32
#define HDIM  128
#define BK    32                 // K floats per sub-tile -> 128B rows
#define BN    40                 // smem B rows per sub-tile (33 live + 7 pad)
#define STAGES 4                 // each stage = 2 sub-tiles (64 k-floats)
#define NT2   (NROWS / (2 * BK)) // 256 double-tiles
#define SUBA  (128 * 128)        // 16384 per A sub-tile
#define SUBB  (BN * 128)         // 5120 per B sub-tile
#define STAGE_BYTES (2 * SUBA + 2 * SUBB)           // 43008
#define SMEM_TOTAL  (1024 + STAGES * STAGE_BYTES)   // 173056

// device scratch
__device__ float g_msgB[BN * NROWS];   // [col][k]; cols0-31 tf32 msg, col32=1

// ---------------- PTX helpers ----------------
__device__ __forceinline__ void cp16(uint32_t dst, const void* src) {
    asm volatile("cp.async.cg.shared.global [%0], [%1], 16;" :: "r"(dst), "l"(src) : "memory");
}
__device__ __forceinline__ float tf32_rna(float x) {
    uint32_t r;
    asm("cvt.rna.tf32.f32 %0, %1;" : "=r"(r) : "f"(x));
    return __uint_as_float(r);
}
__device__ __forceinline__ void ldsm_x4(uint32_t& r0, uint32_t& r1, uint32_t& r2, uint32_t& r3,
                                        uint32_t addr) {
    asm volatile("ldmatrix.sync.aligned.m8n8.x4.shared.b16 {%0,%1,%2,%3}, [%4];"
                 : "=r"(r0), "=r"(r1), "=r"(r2), "=r"(r3) : "r"(addr));
}
__device__ __forceinline__ void ldsm_x2(uint32_t& r0, uint32_t& r1, uint32_t addr) {
    asm volatile("ldmatrix.sync.aligned.m8n8.x2.shared.b16 {%0,%1}, [%2];"
                 : "=r"(r0), "=r"(r1) : "r"(addr));
}
__device__ __forceinline__ void mma_tf32(float* c, uint32_t a0, uint32_t a1,
                                         uint32_t a2, uint32_t a3,
                                         uint32_t b0, uint32_t b1) {
    asm volatile(
        "mma.sync.aligned.m16n8k8.row.col.f32.tf32.tf32.f32 "
        "{%0,%1,%2,%3}, {%4,%5,%6,%7}, {%8,%9}, {%0,%1,%2,%3};"
        : "+f"(c[0]), "+f"(c[1]), "+f"(c[2]), "+f"(c[3])
        : "r"(a0), "r"(a1), "r"(a2), "r"(a3), "r"(b0), "r"(b1));
}

// ==================== Kernel 1: message MLP (round-9 proven) ====================
__global__ __launch_bounds__(128) void msg_kernel(
    const float* __restrict__ states, const float* __restrict__ W1,
    const float* __restrict__ b1,     const float* __restrict__ W2,
    const float* __restrict__ b2)
{
    __shared__ float sW1[DDIM * HDIM];
    __shared__ float sW2[HDIM * DDIM];
    const int tid = threadIdx.x;
    for (int i = tid; i < DDIM * HDIM; i += 128) sW1[i] = W1[i];
    for (int i = tid; i < HDIM * DDIM; i += 128) sW2[i] = W2[i];
    __syncthreads();

    const int row = blockIdx.x * 128 + tid;
    float s[DDIM];
    const float4* sp = reinterpret_cast<const float4*>(states + (size_t)row * DDIM);
    #pragma unroll
    for (int j4 = 0; j4 < DDIM / 4; j4++) {
        float4 v = sp[j4];
        s[4*j4+0] = v.x; s[4*j4+1] = v.y; s[4*j4+2] = v.z; s[4*j4+3] = v.w;
    }
    float m[DDIM];
    #pragma unroll
    for (int d = 0; d < DDIM; d++) m[d] = __ldg(&b2[d]);

    #pragma unroll 4
    for (int hg = 0; hg < HDIM / 4; hg++) {
        float4 hid = __ldg(reinterpret_cast<const float4*>(b1) + hg);
        #pragma unroll
        for (int j = 0; j < DDIM; j++) {
            float4 w = *reinterpret_cast<const float4*>(&sW1[j * HDIM + 4 * hg]);
            hid.x += s[j] * w.x; hid.y += s[j] * w.y;
            hid.z += s[j] * w.z; hid.w += s[j] * w.w;
        }
        float rr[4] = {fmaxf(hid.x, 0.f), fmaxf(hid.y, 0.f),
                       fmaxf(hid.z, 0.f), fmaxf(hid.w, 0.f)};
        #pragma unroll
        for (int e = 0; e < 4; e++) {
            float r = rr[e];
            #pragma unroll
            for (int d4 = 0; d4 < DDIM / 4; d4++) {
                float4 w = *reinterpret_cast<const float4*>(&sW2[(4*hg+e) * DDIM + 4*d4]);
                m[4*d4+0] += r * w.x; m[4*d4+1] += r * w.y;
                m[4*d4+2] += r * w.z; m[4*d4+3] += r * w.w;
            }
        }
    }
    #pragma unroll
    for (int d = 0; d < DDIM; d++)
        g_msgB[(size_t)d * NROWS + row] = tf32_rna(m[d]);
    g_msgB[(size_t)32 * NROWS + row] = 1.0f;          // degree column
}

// ==================== Kernel 2: agg (round-10 pipeline) + fused update MLP ==========
__device__ __forceinline__ void fill_stage2(const float* __restrict__ adj, size_t rowBase,
                                            int t2, uint32_t stage, int tid)
{
    const float* aSrc = adj + rowBase * NROWS + (size_t)t2 * (2 * BK);
    #pragma unroll
    for (int i = 0; i < 8; i++) {                     // A: 2048 16B chunks
        int c = tid + 256 * i;
        int sub = c >> 10, w = c & 1023;
        int r = w >> 3, k4 = w & 7;
        uint32_t dst = stage + sub * SUBA + ((r * 8 + (k4 ^ (r & 7))) << 4);
        cp16(dst, aSrc + (size_t)r * NROWS + sub * BK + (k4 << 2));
    }
    #pragma unroll
    for (int i = 0; i < 3; i++) {                     // B: 528 chunks (2 x 33 rows)
        int c = tid + 256 * i;
        if (i < 2 || c < 528) {
            int sub = c >= 264, w = c - 264 * sub;
            int r = w >> 3, k4 = w & 7;
            uint32_t dst = stage + 2 * SUBA + sub * SUBB + ((r * 8 + (k4 ^ (r & 7))) << 4);
            cp16(dst, g_msgB + (size_t)r * NROWS + (size_t)t2 * (2 * BK) + sub * BK + (k4 << 2));
        }
    }
    asm volatile("cp.async.commit_group;" ::: "memory");
}

__global__ __launch_bounds__(256, 1) void agg_kernel(
    const float* __restrict__ adj,   const float* __restrict__ states,
    const float* __restrict__ uW1,   const float* __restrict__ ub1,
    const float* __restrict__ uW2,   const float* __restrict__ ub2,
    float* __restrict__ out)
{
    extern __shared__ char smem[];
    uint32_t sraw = (uint32_t)__cvta_generic_to_shared(smem);
    const uint32_t stage0 = (sraw + 1023u) & ~1023u;

    const int tid  = threadIdx.x;
    const int wid  = tid >> 5;
    const int lane = tid & 31;
    const size_t rowBase = (size_t)blockIdx.x * 128;

    const int jm = lane >> 3;        // matrix index 0..3
    const int qm = lane & 7;         // row within matrix
    const int hb = jm & 1;           // x2 half select
    const int arow = wid * 16 + (jm >> 1) * 8 + qm;    // A row for this lane

    float acc[5][4];
    #pragma unroll
    for (int nt = 0; nt < 5; nt++)
        #pragma unroll
        for (int e = 0; e < 4; e++) acc[nt][e] = 0.f;

    for (int t = 0; t < STAGES - 1; t++)
        fill_stage2(adj, rowBase, t, stage0 + t * STAGE_BYTES, tid);

    for (int kt2 = 0; kt2 < NT2; kt2++) {
        asm volatile("cp.async.wait_group %0;" :: "n"(STAGES - 2) : "memory");
        __syncthreads();

        const int nxt = kt2 + STAGES - 1;
        if (nxt < NT2)
            fill_stage2(adj, rowBase, nxt,
                        stage0 + (uint32_t)(nxt & (STAGES - 1)) * STAGE_BYTES, tid);

        const uint32_t stg = stage0 + (uint32_t)(kt2 & (STAGES - 1)) * STAGE_BYTES;

        #pragma unroll
        for (int sub = 0; sub < 2; sub++) {
            const uint32_t sA = stg + sub * SUBA;
            const uint32_t sB = stg + 2 * SUBA + sub * SUBB;
            #pragma unroll
            for (int s = 0; s < 4; s++) {
                const int ch  = 2 * s + (jm & 1);
                const int chx = 2 * s + hb;
                uint32_t a0, a1, a2, a3;
                ldsm_x4(a0, a1, a2, a3, sA + ((arow * 8 + (ch ^ (arow & 7))) << 4));
                uint32_t b[10];
                {
                    const int nr0 = (jm >> 1) * 8 + qm;            // tiles 0,1
                    ldsm_x4(b[0], b[1], b[2], b[3],
                            sB + ((nr0 * 8 + (ch ^ (nr0 & 7))) << 4));
                    const int nr1 = 16 + (jm >> 1) * 8 + qm;        // tiles 2,3
                    ldsm_x4(b[4], b[5], b[6], b[7],
                            sB + ((nr1 * 8 + (ch ^ (nr1 & 7))) << 4));
                    const int nr2 = 32 + qm;                        // tile 4 (degree)
                    ldsm_x2(b[8], b[9], sB + ((nr2 * 8 + (chx ^ (nr2 & 7))) << 4));
                }
                #pragma unroll
                for (int nt = 0; nt < 5; nt++)
                    mma_tf32(acc[nt], a0, a2, a1, a3, b[2*nt], b[2*nt+1]);
            }
        }
    }
    asm volatile("cp.async.wait_group 0;" ::: "memory");
    __syncthreads();                                   // pipeline smem now dead

    // ---------- epilogue part 1: degree-normalize, stash agg in smem ----------
    // smem reuse: [sW1u 64x128][sW2u 128x32][sAgg 128x34][ex 4x64x33]
    float* sW1u = reinterpret_cast<float*>(smem + (stage0 - sraw));
    float* sW2u = sW1u + 64 * HDIM;
    float* sAgg = sW2u + HDIM * DDIM;
    float* ex   = sAgg + 128 * 34;

    const int srcLane = lane & ~3;
    float dlo = __shfl_sync(0xffffffffu, acc[4][0], srcLane);
    float dhi = __shfl_sync(0xffffffffu, acc[4][2], srcLane);
    float rdlo = 1.0f / fmaxf(dlo, 1.0f);
    float rdhi = 1.0f / fmaxf(dhi, 1.0f);

    const int rlo = wid * 16 + (lane >> 2);
    const int rhi = rlo + 8;
    const int coff = 2 * (lane & 3);
    #pragma unroll
    for (int nt = 0; nt < 4; nt++) {
        float2 olo = {acc[nt][0] * rdlo, acc[nt][1] * rdlo};
        float2 ohi = {acc[nt][2] * rdhi, acc[nt][3] * rdhi};
        *reinterpret_cast<float2*>(&sAgg[rlo * 34 + 8 * nt + coff]) = olo;
        *reinterpret_cast<float2*>(&sAgg[rhi * 34 + 8 * nt + coff]) = ohi;
    }
    // cooperative weight load (disjoint smem region; no race with sAgg writes)
    for (int i = tid; i < 2 * DDIM * HDIM; i += 256) sW1u[i] = uW1[i];
    for (int i = tid; i < HDIM * DDIM; i += 256)     sW2u[i] = uW2[i];
    __syncthreads();

    // ---------- epilogue part 2: update MLP (round-7 pattern, 2 x 64-row halves) ----
    const int g2 = wid >> 2, q = wid & 3;              // q uniform per warp
    #pragma unroll
    for (int half = 0; half < 2; half++) {
        const int rowL = half * 64 + g2 * 32 + lane;   // 0..127
        const size_t row = rowBase + rowL;

        float x[2 * DDIM];
        const float4* sp = reinterpret_cast<const float4*>(states + row * DDIM);
        #pragma unroll
        for (int j4 = 0; j4 < 8; j4++) {
            float4 v = sp[j4];
            x[4*j4+0] = v.x; x[4*j4+1] = v.y; x[4*j4+2] = v.z; x[4*j4+3] = v.w;
        }
        #pragma unroll
        for (int j2 = 0; j2 < 16; j2++) {
            float2 a = *reinterpret_cast<const float2*>(&sAgg[rowL * 34 + 2 * j2]);
            x[DDIM + 2*j2]     = a.x;
            x[DDIM + 2*j2 + 1] = a.y;
        }
        float hid[32];
        #pragma unroll
        for (int h4 = 0; h4 < 8; h4++) {
            float4 b = __ldg(reinterpret_cast<const float4*>(ub1 + q * 32) + h4);
            hid[4*h4+0] = b.x; hid[4*h4+1] = b.y; hid[4*h4+2] = b.z; hid[4*h4+3] = b.w;
        }
        #pragma unroll
        for (int j = 0; j < 2 * DDIM; j++) {
            const float xj = x[j];
            #pragma unroll
            for (int h4 = 0; h4 < 8; h4++) {
                float4 w = *reinterpret_cast<const float4*>(&sW1u[j * HDIM + q * 32 + 4 * h4]);
                hid[4*h4+0] += xj * w.x; hid[4*h4+1] += xj * w.y;
                hid[4*h4+2] += xj * w.z; hid[4*h4+3] += xj * w.w;
            }
        }
        float m[DDIM];
        #pragma unroll
        for (int d = 0; d < DDIM; d++) m[d] = 0.f;
        #pragma unroll
        for (int h = 0; h < 32; h++) {
            float r = fmaxf(hid[h], 0.f);
            #pragma unroll
            for (int d4 = 0; d4 < 8; d4++) {
                float4 w = *reinterpret_cast<const float4*>(&sW2u[(q * 32 + h) * DDIM + 4 * d4]);
                m[4*d4+0] += r * w.x; m[4*d4+1] += r * w.y;
                m[4*d4+2] += r * w.z; m[4*d4+3] += r * w.w;
            }
        }
        const int rowE = g2 * 32 + lane;               // 0..63 within half
        #pragma unroll
        for (int d = 0; d < DDIM; d++)
            ex[(q * 64 + rowE) * 33 + d] = m[d];
        __syncthreads();

        // reduce across q and store
        const int row2 = tid >> 2;                      // 0..63
        const int dg   = (tid & 3) * 8;
        const size_t rowG = rowBase + half * 64 + row2;
        float o[8];
        #pragma unroll
        for (int e = 0; e < 8; e++) {
            const int d = dg + e;
            float v = __ldg(&ub2[d]);
            #pragma unroll
            for (int qq = 0; qq < 4; qq++)
                v += ex[(qq * 64 + row2) * 33 + d];
            o[e] = v;
        }
        float4* op = reinterpret_cast<float4*>(out + rowG * DDIM + dg);
        op[0] = make_float4(o[0], o[1], o[2], o[3]);
        op[1] = make_float4(o[4], o[5], o[6], o[7]);
        __syncthreads();                                // ex reuse next half
    }
}

// ==================== launch ====================
extern "C" void kernel_launch(void* const* d_in, const int* in_sizes, int n_in,
                              void* d_out, int out_size)
{
    const float* states = (const float*)d_in[0];
    const float* adj    = (const float*)d_in[1];
    const float* mW1    = (const float*)d_in[2];
    const float* mb1    = (const float*)d_in[3];
    const float* mW2    = (const float*)d_in[4];
    const float* mb2    = (const float*)d_in[5];
    const float* uW1    = (const float*)d_in[6];
    const float* ub1    = (const float*)d_in[7];
    const float* uW2    = (const float*)d_in[8];
    const float* ub2    = (const float*)d_in[9];
    float* out = (float*)d_out;

    cudaFuncSetAttribute(agg_kernel, cudaFuncAttributeMaxDynamicSharedMemorySize, SMEM_TOTAL);

    msg_kernel<<<NROWS / 128, 128>>>(states, mW1, mb1, mW2, mb2);
    agg_kernel<<<NROWS / 128, 256, SMEM_TOTAL>>>(adj, states, uW1, ub1, uW2, ub2, out);
}

// round 13
// speedup vs baseline: 1.1416x; 1.1416x over previous
#include <cuda_runtime.h>
#include <cstdint>

#define NROWS 16384
#define DDIM  32
#define HDIM  128
#define BK    32                 // K floats per sub-tile -> 128B rows
#define BN    32                 // B rows: 32 msg cols (degree now from A-side FADD)
#define STAGES 4                 // each stage = 2 sub-tiles (64 k-floats)
#define NT2   (NROWS / (2 * BK)) // 256 double-tiles
#define SUBA  (128 * 128)        // 16384 per A sub-tile
#define SUBB  (BN * 128)         // 4096 per B sub-tile
#define STAGE_BYTES (2 * SUBA + 2 * SUBB)           // 40960
#define SMEM_TOTAL  (1024 + STAGES * STAGE_BYTES)   // 164864

// update MLP smem
#define EX_STRIDE 33
#define EX_BYTES  (4 * 64 * EX_STRIDE * 4)
#define UPD_SMEM  (2 * DDIM * HDIM * 4 + HDIM * DDIM * 4 + EX_BYTES)  // 82944

// device scratch
__device__ float g_msgB[BN * NROWS];   // [col][k]; 32 tf32 msg columns
__device__ float g_agg [NROWS * DDIM];

// ---------------- PTX helpers ----------------
__device__ __forceinline__ void cp16(uint32_t dst, const void* src) {
    asm volatile("cp.async.cg.shared.global [%0], [%1], 16;" :: "r"(dst), "l"(src) : "memory");
}
__device__ __forceinline__ float tf32_rna(float x) {
    uint32_t r;
    asm("cvt.rna.tf32.f32 %0, %1;" : "=r"(r) : "f"(x));
    return __uint_as_float(r);
}
__device__ __forceinline__ void ldsm_x4(uint32_t& r0, uint32_t& r1, uint32_t& r2, uint32_t& r3,
                                        uint32_t addr) {
    asm volatile("ldmatrix.sync.aligned.m8n8.x4.shared.b16 {%0,%1,%2,%3}, [%4];"
                 : "=r"(r0), "=r"(r1), "=r"(r2), "=r"(r3) : "r"(addr));
}
__device__ __forceinline__ void mma_tf32(float* c, uint32_t a0, uint32_t a1,
                                         uint32_t a2, uint32_t a3,
                                         uint32_t b0, uint32_t b1) {
    asm volatile(
        "mma.sync.aligned.m16n8k8.row.col.f32.tf32.tf32.f32 "
        "{%0,%1,%2,%3}, {%4,%5,%6,%7}, {%8,%9}, {%0,%1,%2,%3};"
        : "+f"(c[0]), "+f"(c[1]), "+f"(c[2]), "+f"(c[3])
        : "r"(a0), "r"(a1), "r"(a2), "r"(a3), "r"(b0), "r"(b1));
}

// ==================== Kernel 1: message MLP (round-9 proven, no aux columns) ==========
__global__ __launch_bounds__(128) void msg_kernel(
    const float* __restrict__ states, const float* __restrict__ W1,
    const float* __restrict__ b1,     const float* __restrict__ W2,
    const float* __restrict__ b2)
{
    __shared__ float sW1[DDIM * HDIM];
    __shared__ float sW2[HDIM * DDIM];
    const int tid = threadIdx.x;
    for (int i = tid; i < DDIM * HDIM; i += 128) sW1[i] = W1[i];
    for (int i = tid; i < HDIM * DDIM; i += 128) sW2[i] = W2[i];
    __syncthreads();

    const int row = blockIdx.x * 128 + tid;
    float s[DDIM];
    const float4* sp = reinterpret_cast<const float4*>(states + (size_t)row * DDIM);
    #pragma unroll
    for (int j4 = 0; j4 < DDIM / 4; j4++) {
        float4 v = sp[j4];
        s[4*j4+0] = v.x; s[4*j4+1] = v.y; s[4*j4+2] = v.z; s[4*j4+3] = v.w;
    }
    float m[DDIM];
    #pragma unroll
    for (int d = 0; d < DDIM; d++) m[d] = __ldg(&b2[d]);

    #pragma unroll 4
    for (int hg = 0; hg < HDIM / 4; hg++) {
        float4 hid = __ldg(reinterpret_cast<const float4*>(b1) + hg);
        #pragma unroll
        for (int j = 0; j < DDIM; j++) {
            float4 w = *reinterpret_cast<const float4*>(&sW1[j * HDIM + 4 * hg]);
            hid.x += s[j] * w.x; hid.y += s[j] * w.y;
            hid.z += s[j] * w.z; hid.w += s[j] * w.w;
        }
        float rr[4] = {fmaxf(hid.x, 0.f), fmaxf(hid.y, 0.f),
                       fmaxf(hid.z, 0.f), fmaxf(hid.w, 0.f)};
        #pragma unroll
        for (int e = 0; e < 4; e++) {
            float r = rr[e];
            #pragma unroll
            for (int d4 = 0; d4 < DDIM / 4; d4++) {
                float4 w = *reinterpret_cast<const float4*>(&sW2[(4*hg+e) * DDIM + 4*d4]);
                m[4*d4+0] += r * w.x; m[4*d4+1] += r * w.y;
                m[4*d4+2] += r * w.z; m[4*d4+3] += r * w.w;
            }
        }
    }
    #pragma unroll
    for (int d = 0; d < DDIM; d++)
        g_msgB[(size_t)d * NROWS + row] = tf32_rna(m[d]);
}

// ==================== Kernel 2: tf32 aggregation, degree from A-fragments ==========
__device__ __forceinline__ void fill_stage2(const float* __restrict__ adj, size_t rowBase,
                                            int t2, uint32_t stage, int tid)
{
    const float* aSrc = adj + rowBase * NROWS + (size_t)t2 * (2 * BK);
    #pragma unroll
    for (int i = 0; i < 8; i++) {                     // A: 2048 16B chunks
        int c = tid + 256 * i;
        int sub = c >> 10, w = c & 1023;
        int r = w >> 3, k4 = w & 7;
        uint32_t dst = stage + sub * SUBA + ((r * 8 + (k4 ^ (r & 7))) << 4);
        cp16(dst, aSrc + (size_t)r * NROWS + sub * BK + (k4 << 2));
    }
    #pragma unroll
    for (int i = 0; i < 2; i++) {                     // B: 512 chunks (2 x 32 rows)
        int c = tid + 256 * i;
        int sub = c >> 8, w = c & 255;
        int r = w >> 3, k4 = w & 7;
        uint32_t dst = stage + 2 * SUBA + sub * SUBB + ((r * 8 + (k4 ^ (r & 7))) << 4);
        cp16(dst, g_msgB + (size_t)r * NROWS + (size_t)t2 * (2 * BK) + sub * BK + (k4 << 2));
    }
    asm volatile("cp.async.commit_group;" ::: "memory");
}

__global__ __launch_bounds__(256, 1) void agg_kernel(const float* __restrict__ adj)
{
    extern __shared__ char smem[];
    uint32_t sraw = (uint32_t)__cvta_generic_to_shared(smem);
    const uint32_t stage0 = (sraw + 1023u) & ~1023u;

    const int tid  = threadIdx.x;
    const int wid  = tid >> 5;
    const int lane = tid & 31;
    const size_t rowBase = (size_t)blockIdx.x * 128;

    const int jm = lane >> 3;        // matrix index 0..3
    const int qm = lane & 7;         // row within matrix
    const int arow = wid * 16 + (jm >> 1) * 8 + qm;    // A row for this lane

    float acc[4][4];
    #pragma unroll
    for (int nt = 0; nt < 4; nt++)
        #pragma unroll
        for (int e = 0; e < 4; e++) acc[nt][e] = 0.f;
    float dlo = 0.f, dhi = 0.f;      // degree partials: rows (lane>>2), (lane>>2)+8

    for (int t = 0; t < STAGES - 1; t++)
        fill_stage2(adj, rowBase, t, stage0 + t * STAGE_BYTES, tid);

    for (int kt2 = 0; kt2 < NT2; kt2++) {
        asm volatile("cp.async.wait_group %0;" :: "n"(STAGES - 2) : "memory");
        __syncthreads();

        const int nxt = kt2 + STAGES - 1;
        if (nxt < NT2)
            fill_stage2(adj, rowBase, nxt,
                        stage0 + (uint32_t)(nxt & (STAGES - 1)) * STAGE_BYTES, tid);

        const uint32_t stg = stage0 + (uint32_t)(kt2 & (STAGES - 1)) * STAGE_BYTES;

        #pragma unroll
        for (int sub = 0; sub < 2; sub++) {
            const uint32_t sA = stg + sub * SUBA;
            const uint32_t sB = stg + 2 * SUBA + sub * SUBB;
            #pragma unroll
            for (int s = 0; s < 4; s++) {
                const int ch = 2 * s + (jm & 1);
                uint32_t a0, a1, a2, a3;
                ldsm_x4(a0, a1, a2, a3, sA + ((arow * 8 + (ch ^ (arow & 7))) << 4));
                // degree: r0,r1 = rows 0-7 (k 0-3 / 4-7); r2,r3 = rows 8-15
                dlo += __uint_as_float(a0) + __uint_as_float(a1);
                dhi += __uint_as_float(a2) + __uint_as_float(a3);
                uint32_t b[8];
                {
                    const int nr0 = (jm >> 1) * 8 + qm;            // tiles 0,1
                    ldsm_x4(b[0], b[1], b[2], b[3],
                            sB + ((nr0 * 8 + (ch ^ (nr0 & 7))) << 4));
                    const int nr1 = 16 + (jm >> 1) * 8 + qm;        // tiles 2,3
                    ldsm_x4(b[4], b[5], b[6], b[7],
                            sB + ((nr1 * 8 + (ch ^ (nr1 & 7))) << 4));
                }
                #pragma unroll
                for (int nt = 0; nt < 4; nt++)
                    mma_tf32(acc[nt], a0, a2, a1, a3, b[2*nt], b[2*nt+1]);
            }
        }
    }

    // reduce degree across the 4 lanes sharing each row (k-column groups)
    dlo += __shfl_xor_sync(0xffffffffu, dlo, 1);
    dlo += __shfl_xor_sync(0xffffffffu, dlo, 2);
    dhi += __shfl_xor_sync(0xffffffffu, dhi, 1);
    dhi += __shfl_xor_sync(0xffffffffu, dhi, 2);
    const float rdlo = 1.0f / fmaxf(dlo, 1.0f);
    const float rdhi = 1.0f / fmaxf(dhi, 1.0f);

    const size_t rlo = rowBase + (size_t)(wid * 16 + (lane >> 2));
    const size_t rhi = rlo + 8;
    const int coff = 2 * (lane & 3);
    #pragma unroll
    for (int nt = 0; nt < 4; nt++) {
        float2 olo = {acc[nt][0] * rdlo, acc[nt][1] * rdlo};
        float2 ohi = {acc[nt][2] * rdhi, acc[nt][3] * rdhi};
        *reinterpret_cast<float2*>(&g_agg[rlo * DDIM + 8 * nt + coff]) = olo;
        *reinterpret_cast<float2*>(&g_agg[rhi * DDIM + 8 * nt + coff]) = ohi;
    }
}

// ==================== Kernel 3: update MLP (round-7 warp-sliced, proven) ==========
__global__ __launch_bounds__(256) void upd_kernel(
    const float* __restrict__ states, const float* __restrict__ W1,
    const float* __restrict__ b1,     const float* __restrict__ W2,
    const float* __restrict__ b2,     float* __restrict__ out)
{
    extern __shared__ float sm[];
    float* sW1 = sm;                                       // [64][128]
    float* sW2 = sm + 2 * DDIM * HDIM;                     // [128][32]
    float* ex  = sm + 2 * DDIM * HDIM + HDIM * DDIM;       // [4][64][33]

    const int tid = threadIdx.x;
    for (int i = tid; i < 2 * DDIM * HDIM; i += 256) sW1[i] = W1[i];
    for (int i = tid; i < HDIM * DDIM; i += 256)     sW2[i] = W2[i];
    __syncthreads();

    const int wid  = tid >> 5, lane = tid & 31;
    const int g = wid >> 2, q = wid & 3;
    const int rowL = g * 32 + lane;
    const int row  = blockIdx.x * 64 + rowL;

    float x[2 * DDIM];
    const float4* sp = reinterpret_cast<const float4*>(states + (size_t)row * DDIM);
    const float4* gp = reinterpret_cast<const float4*>(g_agg  + (size_t)row * DDIM);
    #pragma unroll
    for (int j4 = 0; j4 < 8; j4++) {
        float4 v = sp[j4];
        x[4*j4+0] = v.x; x[4*j4+1] = v.y; x[4*j4+2] = v.z; x[4*j4+3] = v.w;
        float4 gg = gp[j4];
        x[DDIM+4*j4+0] = gg.x; x[DDIM+4*j4+1] = gg.y;
        x[DDIM+4*j4+2] = gg.z; x[DDIM+4*j4+3] = gg.w;
    }
    float hid[32];
    #pragma unroll
    for (int h4 = 0; h4 < 8; h4++) {
        float4 b = __ldg(reinterpret_cast<const float4*>(b1 + q * 32) + h4);
        hid[4*h4+0] = b.x; hid[4*h4+1] = b.y; hid[4*h4+2] = b.z; hid[4*h4+3] = b.w;
    }
    #pragma unroll
    for (int j = 0; j < 2 * DDIM; j++) {
        const float xj = x[j];
        #pragma unroll
        for (int h4 = 0; h4 < 8; h4++) {
            float4 w = *reinterpret_cast<const float4*>(&sW1[j * HDIM + q * 32 + 4 * h4]);
            hid[4*h4+0] += xj * w.x; hid[4*h4+1] += xj * w.y;
            hid[4*h4+2] += xj * w.z; hid[4*h4+3] += xj * w.w;
        }
    }
    float m[DDIM];
    #pragma unroll
    for (int d = 0; d < DDIM; d++) m[d] = 0.f;
    #pragma unroll
    for (int h = 0; h < 32; h++) {
        float r = fmaxf(hid[h], 0.f);
        #pragma unroll
        for (int d4 = 0; d4 < 8; d4++) {
            float4 w = *reinterpret_cast<const float4*>(&sW2[(q * 32 + h) * DDIM + 4 * d4]);
            m[4*d4+0] += r * w.x; m[4*d4+1] += r * w.y;
            m[4*d4+2] += r * w.z; m[4*d4+3] += r * w.w;
        }
    }
    #pragma unroll
    for (int d = 0; d < DDIM; d++)
        ex[(q * 64 + rowL) * EX_STRIDE + d] = m[d];
    __syncthreads();

    const int row2 = tid >> 2;
    const int dg   = (tid & 3) * 8;
    const size_t rowG = (size_t)blockIdx.x * 64 + row2;
    float o[8];
    #pragma unroll
    for (int e = 0; e < 8; e++) {
        const int d = dg + e;
        float v = __ldg(&b2[d]);
        #pragma unroll
        for (int qq = 0; qq < 4; qq++)
            v += ex[(qq * 64 + row2) * EX_STRIDE + d];
        o[e] = v;
    }
    float4* op = reinterpret_cast<float4*>(out + rowG * DDIM + dg);
    op[0] = make_float4(o[0], o[1], o[2], o[3]);
    op[1] = make_float4(o[4], o[5], o[6], o[7]);
}

// ==================== launch ====================
extern "C" void kernel_launch(void* const* d_in, const int* in_sizes, int n_in,
                              void* d_out, int out_size)
{
    const float* states = (const float*)d_in[0];
    const float* adj    = (const float*)d_in[1];
    const float* mW1    = (const float*)d_in[2];
    const float* mb1    = (const float*)d_in[3];
    const float* mW2    = (const float*)d_in[4];
    const float* mb2    = (const float*)d_in[5];
    const float* uW1    = (const float*)d_in[6];
    const float* ub1    = (const float*)d_in[7];
    const float* uW2    = (const float*)d_in[8];
    const float* ub2    = (const float*)d_in[9];
    float* out = (float*)d_out;

    cudaFuncSetAttribute(agg_kernel, cudaFuncAttributeMaxDynamicSharedMemorySize, SMEM_TOTAL);
    cudaFuncSetAttribute(upd_kernel, cudaFuncAttributeMaxDynamicSharedMemorySize, UPD_SMEM);

    msg_kernel<<<NROWS / 128, 128>>>(states, mW1, mb1, mW2, mb2);
    agg_kernel<<<NROWS / 128, 256, SMEM_TOTAL>>>(adj);
    upd_kernel<<<NROWS / 64, 256, UPD_SMEM>>>(states, uW1, ub1, uW2, ub2, out);
}

// round 14
// speedup vs baseline: 1.1648x; 1.0203x over previous
#include <cuda_runtime.h>
#include <cstdint>

#define NROWS 16384
#define DDIM  32
#define HDIM  128
#define BK    32                 // K floats per sub-tile -> 128B rows
#define BN    32                 // B rows: 32 msg cols (degree from A-side FADD)
#define STAGES 5                 // each stage = 2 sub-tiles (64 k-floats)
#define NT2   (NROWS / (2 * BK)) // 256 double-tiles
#define SUBA  (128 * 128)        // 16384 per A sub-tile
#define SUBB  (BN * 128)         // 4096 per B sub-tile
#define STAGE_BYTES (2 * SUBA + 2 * SUBB)           // 40960
#define SMEM_TOTAL  (1024 + STAGES * STAGE_BYTES)   // 205824

// update MLP smem
#define EX_STRIDE 33
#define EX_BYTES  (4 * 64 * EX_STRIDE * 4)
#define UPD_SMEM  (2 * DDIM * HDIM * 4 + HDIM * DDIM * 4 + EX_BYTES)  // 82944

// device scratch
__device__ float g_msgB[BN * NROWS];   // [col][k]; 32 tf32 msg columns
__device__ float g_agg [NROWS * DDIM];

// ---------------- PTX helpers ----------------
__device__ __forceinline__ void cp16(uint32_t dst, const void* src) {
    asm volatile("cp.async.cg.shared.global [%0], [%1], 16;" :: "r"(dst), "l"(src) : "memory");
}
__device__ __forceinline__ float tf32_rna(float x) {
    uint32_t r;
    asm("cvt.rna.tf32.f32 %0, %1;" : "=r"(r) : "f"(x));
    return __uint_as_float(r);
}
__device__ __forceinline__ void ldsm_x4(uint32_t& r0, uint32_t& r1, uint32_t& r2, uint32_t& r3,
                                        uint32_t addr) {
    asm volatile("ldmatrix.sync.aligned.m8n8.x4.shared.b16 {%0,%1,%2,%3}, [%4];"
                 : "=r"(r0), "=r"(r1), "=r"(r2), "=r"(r3) : "r"(addr));
}
__device__ __forceinline__ void mma_tf32(float* c, uint32_t a0, uint32_t a1,
                                         uint32_t a2, uint32_t a3,
                                         uint32_t b0, uint32_t b1) {
    asm volatile(
        "mma.sync.aligned.m16n8k8.row.col.f32.tf32.tf32.f32 "
        "{%0,%1,%2,%3}, {%4,%5,%6,%7}, {%8,%9}, {%0,%1,%2,%3};"
        : "+f"(c[0]), "+f"(c[1]), "+f"(c[2]), "+f"(c[3])
        : "r"(a0), "r"(a1), "r"(a2), "r"(a3), "r"(b0), "r"(b1));
}

// ==================== Kernel 1: message MLP (round-9 proven) ====================
__global__ __launch_bounds__(128) void msg_kernel(
    const float* __restrict__ states, const float* __restrict__ W1,
    const float* __restrict__ b1,     const float* __restrict__ W2,
    const float* __restrict__ b2)
{
    __shared__ float sW1[DDIM * HDIM];
    __shared__ float sW2[HDIM * DDIM];
    const int tid = threadIdx.x;
    for (int i = tid; i < DDIM * HDIM; i += 128) sW1[i] = W1[i];
    for (int i = tid; i < HDIM * DDIM; i += 128) sW2[i] = W2[i];
    __syncthreads();

    const int row = blockIdx.x * 128 + tid;
    float s[DDIM];
    const float4* sp = reinterpret_cast<const float4*>(states + (size_t)row * DDIM);
    #pragma unroll
    for (int j4 = 0; j4 < DDIM / 4; j4++) {
        float4 v = sp[j4];
        s[4*j4+0] = v.x; s[4*j4+1] = v.y; s[4*j4+2] = v.z; s[4*j4+3] = v.w;
    }
    float m[DDIM];
    #pragma unroll
    for (int d = 0; d < DDIM; d++) m[d] = __ldg(&b2[d]);

    #pragma unroll 4
    for (int hg = 0; hg < HDIM / 4; hg++) {
        float4 hid = __ldg(reinterpret_cast<const float4*>(b1) + hg);
        #pragma unroll
        for (int j = 0; j < DDIM; j++) {
            float4 w = *reinterpret_cast<const float4*>(&sW1[j * HDIM + 4 * hg]);
            hid.x += s[j] * w.x; hid.y += s[j] * w.y;
            hid.z += s[j] * w.z; hid.w += s[j] * w.w;
        }
        float rr[4] = {fmaxf(hid.x, 0.f), fmaxf(hid.y, 0.f),
                       fmaxf(hid.z, 0.f), fmaxf(hid.w, 0.f)};
        #pragma unroll
        for (int e = 0; e < 4; e++) {
            float r = rr[e];
            #pragma unroll
            for (int d4 = 0; d4 < DDIM / 4; d4++) {
                float4 w = *reinterpret_cast<const float4*>(&sW2[(4*hg+e) * DDIM + 4*d4]);
                m[4*d4+0] += r * w.x; m[4*d4+1] += r * w.y;
                m[4*d4+2] += r * w.z; m[4*d4+3] += r * w.w;
            }
        }
    }
    #pragma unroll
    for (int d = 0; d < DDIM; d++)
        g_msgB[(size_t)d * NROWS + row] = tf32_rna(m[d]);
}

// ==================== Kernel 2: tf32 aggregation, 5-deep double-tile pipeline ======
__device__ __forceinline__ void fill_stage2(const float* __restrict__ adj, size_t rowBase,
                                            int t2, uint32_t stage, int tid)
{
    const float* aSrc = adj + rowBase * NROWS + (size_t)t2 * (2 * BK);
    #pragma unroll
    for (int i = 0; i < 8; i++) {                     // A: 2048 16B chunks
        int c = tid + 256 * i;
        int sub = c >> 10, w = c & 1023;
        int r = w >> 3, k4 = w & 7;
        uint32_t dst = stage + sub * SUBA + ((r * 8 + (k4 ^ (r & 7))) << 4);
        cp16(dst, aSrc + (size_t)r * NROWS + sub * BK + (k4 << 2));
    }
    #pragma unroll
    for (int i = 0; i < 2; i++) {                     // B: 512 chunks (2 x 32 rows)
        int c = tid + 256 * i;
        int sub = c >> 8, w = c & 255;
        int r = w >> 3, k4 = w & 7;
        uint32_t dst = stage + 2 * SUBA + sub * SUBB + ((r * 8 + (k4 ^ (r & 7))) << 4);
        cp16(dst, g_msgB + (size_t)r * NROWS + (size_t)t2 * (2 * BK) + sub * BK + (k4 << 2));
    }
    asm volatile("cp.async.commit_group;" ::: "memory");
}

__global__ __launch_bounds__(256, 1) void agg_kernel(const float* __restrict__ adj)
{
    extern __shared__ char smem[];
    uint32_t sraw = (uint32_t)__cvta_generic_to_shared(smem);
    const uint32_t stage0 = (sraw + 1023u) & ~1023u;

    const int tid  = threadIdx.x;
    const int wid  = tid >> 5;
    const int lane = tid & 31;
    const size_t rowBase = (size_t)blockIdx.x * 128;

    const int jm = lane >> 3;        // matrix index 0..3
    const int qm = lane & 7;         // row within matrix
    const int arow = wid * 16 + (jm >> 1) * 8 + qm;    // A row for this lane

    float acc[4][4];
    #pragma unroll
    for (int nt = 0; nt < 4; nt++)
        #pragma unroll
        for (int e = 0; e < 4; e++) acc[nt][e] = 0.f;
    float dlo = 0.f, dhi = 0.f;      // degree partials

    for (int t = 0; t < STAGES - 1; t++)
        fill_stage2(adj, rowBase, t, stage0 + t * STAGE_BYTES, tid);

    int bufC = 0;                    // compute slot (wraps mod 5)
    int bufF = STAGES - 1;           // fill slot
    for (int kt2 = 0; kt2 < NT2; kt2++) {
        asm volatile("cp.async.wait_group %0;" :: "n"(STAGES - 2) : "memory");
        __syncthreads();

        const int nxt = kt2 + STAGES - 1;
        if (nxt < NT2)
            fill_stage2(adj, rowBase, nxt, stage0 + (uint32_t)bufF * STAGE_BYTES, tid);
        if (++bufF == STAGES) bufF = 0;

        const uint32_t stg = stage0 + (uint32_t)bufC * STAGE_BYTES;
        if (++bufC == STAGES) bufC = 0;

        #pragma unroll
        for (int sub = 0; sub < 2; sub++) {
            const uint32_t sA = stg + sub * SUBA;
            const uint32_t sB = stg + 2 * SUBA + sub * SUBB;
            #pragma unroll
            for (int s = 0; s < 4; s++) {
                const int ch = 2 * s + (jm & 1);
                uint32_t a0, a1, a2, a3;
                ldsm_x4(a0, a1, a2, a3, sA + ((arow * 8 + (ch ^ (arow & 7))) << 4));
                dlo += __uint_as_float(a0) + __uint_as_float(a1);
                dhi += __uint_as_float(a2) + __uint_as_float(a3);
                uint32_t b[8];
                {
                    const int nr0 = (jm >> 1) * 8 + qm;            // tiles 0,1
                    ldsm_x4(b[0], b[1], b[2], b[3],
                            sB + ((nr0 * 8 + (ch ^ (nr0 & 7))) << 4));
                    const int nr1 = 16 + (jm >> 1) * 8 + qm;        // tiles 2,3
                    ldsm_x4(b[4], b[5], b[6], b[7],
                            sB + ((nr1 * 8 + (ch ^ (nr1 & 7))) << 4));
                }
                #pragma unroll
                for (int nt = 0; nt < 4; nt++)
                    mma_tf32(acc[nt], a0, a2, a1, a3, b[2*nt], b[2*nt+1]);
            }
        }
    }

    // reduce degree across the 4 lanes sharing each row
    dlo += __shfl_xor_sync(0xffffffffu, dlo, 1);
    dlo += __shfl_xor_sync(0xffffffffu, dlo, 2);
    dhi += __shfl_xor_sync(0xffffffffu, dhi, 1);
    dhi += __shfl_xor_sync(0xffffffffu, dhi, 2);
    const float rdlo = 1.0f / fmaxf(dlo, 1.0f);
    const float rdhi = 1.0f / fmaxf(dhi, 1.0f);

    const size_t rlo = rowBase + (size_t)(wid * 16 + (lane >> 2));
    const size_t rhi = rlo + 8;
    const int coff = 2 * (lane & 3);
    #pragma unroll
    for (int nt = 0; nt < 4; nt++) {
        float2 olo = {acc[nt][0] * rdlo, acc[nt][1] * rdlo};
        float2 ohi = {acc[nt][2] * rdhi, acc[nt][3] * rdhi};
        *reinterpret_cast<float2*>(&g_agg[rlo * DDIM + 8 * nt + coff]) = olo;
        *reinterpret_cast<float2*>(&g_agg[rhi * DDIM + 8 * nt + coff]) = ohi;
    }
}

// ==================== Kernel 3: update MLP (round-7 warp-sliced, proven) ==========
__global__ __launch_bounds__(256) void upd_kernel(
    const float* __restrict__ states, const float* __restrict__ W1,
    const float* __restrict__ b1,     const float* __restrict__ W2,
    const float* __restrict__ b2,     float* __restrict__ out)
{
    extern __shared__ float sm[];
    float* sW1 = sm;                                       // [64][128]
    float* sW2 = sm + 2 * DDIM * HDIM;                     // [128][32]
    float* ex  = sm + 2 * DDIM * HDIM + HDIM * DDIM;       // [4][64][33]

    const int tid = threadIdx.x;
    for (int i = tid; i < 2 * DDIM * HDIM; i += 256) sW1[i] = W1[i];
    for (int i = tid; i < HDIM * DDIM; i += 256)     sW2[i] = W2[i];
    __syncthreads();

    const int wid  = tid >> 5, lane = tid & 31;
    const int g = wid >> 2, q = wid & 3;
    const int rowL = g * 32 + lane;
    const int row  = blockIdx.x * 64 + rowL;

    float x[2 * DDIM];
    const float4* sp = reinterpret_cast<const float4*>(states + (size_t)row * DDIM);
    const float4* gp = reinterpret_cast<const float4*>(g_agg  + (size_t)row * DDIM);
    #pragma unroll
    for (int j4 = 0; j4 < 8; j4++) {
        float4 v = sp[j4];
        x[4*j4+0] = v.x; x[4*j4+1] = v.y; x[4*j4+2] = v.z; x[4*j4+3] = v.w;
        float4 gg = gp[j4];
        x[DDIM+4*j4+0] = gg.x; x[DDIM+4*j4+1] = gg.y;
        x[DDIM+4*j4+2] = gg.z; x[DDIM+4*j4+3] = gg.w;
    }
    float hid[32];
    #pragma unroll
    for (int h4 = 0; h4 < 8; h4++) {
        float4 b = __ldg(reinterpret_cast<const float4*>(b1 + q * 32) + h4);
        hid[4*h4+0] = b.x; hid[4*h4+1] = b.y; hid[4*h4+2] = b.z; hid[4*h4+3] = b.w;
    }
    #pragma unroll
    for (int j = 0; j < 2 * DDIM; j++) {
        const float xj = x[j];
        #pragma unroll
        for (int h4 = 0; h4 < 8; h4++) {
            float4 w = *reinterpret_cast<const float4*>(&sW1[j * HDIM + q * 32 + 4 * h4]);
            hid[4*h4+0] += xj * w.x; hid[4*h4+1] += xj * w.y;
            hid[4*h4+2] += xj * w.z; hid[4*h4+3] += xj * w.w;
        }
    }
    float m[DDIM];
    #pragma unroll
    for (int d = 0; d < DDIM; d++) m[d] = 0.f;
    #pragma unroll
    for (int h = 0; h < 32; h++) {
        float r = fmaxf(hid[h], 0.f);
        #pragma unroll
        for (int d4 = 0; d4 < 8; d4++) {
            float4 w = *reinterpret_cast<const float4*>(&sW2[(q * 32 + h) * DDIM + 4 * d4]);
            m[4*d4+0] += r * w.x; m[4*d4+1] += r * w.y;
            m[4*d4+2] += r * w.z; m[4*d4+3] += r * w.w;
        }
    }
    #pragma unroll
    for (int d = 0; d < DDIM; d++)
        ex[(q * 64 + rowL) * EX_STRIDE + d] = m[d];
    __syncthreads();

    const int row2 = tid >> 2;
    const int dg   = (tid & 3) * 8;
    const size_t rowG = (size_t)blockIdx.x * 64 + row2;
    float o[8];
    #pragma unroll
    for (int e = 0; e < 8; e++) {
        const int d = dg + e;
        float v = __ldg(&b2[d]);
        #pragma unroll
        for (int qq = 0; qq < 4; qq++)
            v += ex[(qq * 64 + row2) * EX_STRIDE + d];
        o[e] = v;
    }
    float4* op = reinterpret_cast<float4*>(out + rowG * DDIM + dg);
    op[0] = make_float4(o[0], o[1], o[2], o[3]);
    op[1] = make_float4(o[4], o[5], o[6], o[7]);
}

// ==================== launch ====================
extern "C" void kernel_launch(void* const* d_in, const int* in_sizes, int n_in,
                              void* d_out, int out_size)
{
    const float* states = (const float*)d_in[0];
    const float* adj    = (const float*)d_in[1];
    const float* mW1    = (const float*)d_in[2];
    const float* mb1    = (const float*)d_in[3];
    const float* mW2    = (const float*)d_in[4];
    const float* mb2    = (const float*)d_in[5];
    const float* uW1    = (const float*)d_in[6];
    const float* ub1    = (const float*)d_in[7];
    const float* uW2    = (const float*)d_in[8];
    const float* ub2    = (const float*)d_in[9];
    float* out = (float*)d_out;

    cudaFuncSetAttribute(agg_kernel, cudaFuncAttributeMaxDynamicSharedMemorySize, SMEM_TOTAL);
    cudaFuncSetAttribute(upd_kernel, cudaFuncAttributeMaxDynamicSharedMemorySize, UPD_SMEM);

    msg_kernel<<<NROWS / 128, 128>>>(states, mW1, mb1, mW2, mb2);
    agg_kernel<<<NROWS / 128, 256, SMEM_TOTAL>>>(adj);
    upd_kernel<<<NROWS / 64, 256, UPD_SMEM>>>(states, uW1, ub1, uW2, ub2, out);
}